// round 7
// baseline (speedup 1.0000x reference)
#include <cuda_runtime.h>
#include <cuda_bf16.h>
#include <cuda_pipeline.h>
#include <mma.h>
#include <math.h>

using namespace nvcuda;

// Problem constants
#define B_  2
#define S_  2048
#define D_  1024
#define H_  16
#define DK_ 64
#define M_  (B_*S_)

// GEMM tiling: CTA 128x64, BK=32, 3-stage cp.async ring, 8 warps (32x32 tiles)
#define BM 128
#define BN 64
#define BK 32
#define LDT 40                        // padded smem row, elements (80B)
#define AH_OFF 0
#define AL_OFF (BM*LDT)               // 5120
#define BH_OFF (2*BM*LDT)             // 10240
#define BL_OFF (2*BM*LDT + BN*LDT)    // 12800
#define SE     (2*BM*LDT + 2*BN*LDT)  // 15360 elems per stage
#define GEMM_SMEM (3*SE*2)            // 92160 bytes

// Flash tiling: 64-key tiles, 3-stage ring
#define FSE 8192                      // floats per stage (K 4096 + V 4096)
#define FLASH_SMEM (3*FSE*4)          // 98304 bytes

// Scratch (device globals — no allocation allowed)
__device__ float g_Qp[B_*S_*D_];
__device__ float g_Kp[B_*S_*D_];
__device__ float g_Vp[B_*S_*D_];
__device__ float g_O [B_*S_*D_];
__device__ __nv_bfloat16 g_Xh[M_*D_];
__device__ __nv_bfloat16 g_Xl[M_*D_];
__device__ __nv_bfloat16 g_Wh[D_*D_];
__device__ __nv_bfloat16 g_Wl[D_*D_];

// ---------------------------------------------------------------------------
// fp32 -> (hi, lo) bf16 split.
// ---------------------------------------------------------------------------
__global__ __launch_bounds__(256)
void cvt_split_kernel(const float4* __restrict__ x,
                      __nv_bfloat16* __restrict__ hi,
                      __nv_bfloat16* __restrict__ lo,
                      int n4)
{
    int i = blockIdx.x * blockDim.x + threadIdx.x;
    if (i >= n4) return;
    float4 v = x[i];
    __nv_bfloat16 h0 = __float2bfloat16(v.x);
    __nv_bfloat16 h1 = __float2bfloat16(v.y);
    __nv_bfloat16 h2 = __float2bfloat16(v.z);
    __nv_bfloat16 h3 = __float2bfloat16(v.w);
    __nv_bfloat162 hh0, hh1, ll0, ll1;
    hh0.x = h0; hh0.y = h1; hh1.x = h2; hh1.y = h3;
    ll0.x = __float2bfloat16(v.x - __bfloat162float(h0));
    ll0.y = __float2bfloat16(v.y - __bfloat162float(h1));
    ll1.x = __float2bfloat16(v.z - __bfloat162float(h2));
    ll1.y = __float2bfloat16(v.w - __bfloat162float(h3));
    *(__nv_bfloat162*)&hi[i*4]     = hh0;
    *(__nv_bfloat162*)&hi[i*4 + 2] = hh1;
    *(__nv_bfloat162*)&lo[i*4]     = ll0;
    *(__nv_bfloat162*)&lo[i*4 + 2] = ll1;
}

// ---------------------------------------------------------------------------
// GEMM v3: Y[M,N] = X[M,K] @ W[N,K]^T + bias[N], bf16 hi/lo 3-pass.
// 3-stage cp.async ring -> ONE __syncthreads per K-slab; low reg pressure
// (sequenced A-fragment loads) -> 2 CTAs/SM.
// ---------------------------------------------------------------------------
__device__ __forceinline__ void gemm_issue_tile(
    __nv_bfloat16* sm, int stage,
    const __nv_bfloat16* Xh, const __nv_bfloat16* Xl,
    const __nv_bfloat16* Wh, const __nv_bfloat16* Wl,
    int m0, int n0, int k0, int K, int tid)
{
    __nv_bfloat16* sb = sm + stage * SE;
    for (int p = 0; p < 6; p++) {
        int g = tid + p * 256;               // 0..1535
        if (g < 1024) {                      // A region (hi then lo)
            int hsel = g >> 9;               // 0 hi, 1 lo
            int h = g & 511;
            int row = h >> 2;
            int cc  = h & 3;
            const __nv_bfloat16* src =
                (hsel ? Xl : Xh) + (size_t)(m0 + row) * K + k0 + cc * 8;
            __pipeline_memcpy_async(sb + hsel * AL_OFF + row * LDT + cc * 8, src, 16);
        } else {                             // B region
            int g2 = g - 1024;               // 0..511
            int hsel = g2 >> 8;              // 0 hi, 1 lo
            int h = g2 & 255;
            int row = h >> 2;
            int cc  = h & 3;
            const __nv_bfloat16* src =
                (hsel ? Wl : Wh) + (size_t)(n0 + row) * K + k0 + cc * 8;
            __pipeline_memcpy_async(sb + BH_OFF + hsel * (BN * LDT) + row * LDT + cc * 8,
                                    src, 16);
        }
    }
}

__global__ __launch_bounds__(256)
void gemm_wmma_kernel(const __nv_bfloat16* __restrict__ Xh,
                      const __nv_bfloat16* __restrict__ Xl,
                      const __nv_bfloat16* __restrict__ Wh,
                      const __nv_bfloat16* __restrict__ Wl,
                      const float* __restrict__ bias,
                      float* __restrict__ Y,
                      int M, int N, int K)
{
    extern __shared__ __nv_bfloat16 sm[];
    __shared__ __align__(16) float biasTile[16][72];

    const int tid = threadIdx.x;
    const int wid = tid >> 5;
    const int m0  = blockIdx.y * BM;
    const int n0  = blockIdx.x * BN;
    const int wm  = (wid & 3) * 32;
    const int wn  = (wid >> 2) * 32;

    for (int idx = tid; idx < 16 * 64; idx += 256) {
        int r = idx >> 6;
        int c = idx & 63;
        biasTile[r][c] = bias[n0 + c];
    }
    __syncthreads();

    wmma::fragment<wmma::accumulator, 16, 16, 16, float> acc[2][2];
    for (int mi = 0; mi < 2; mi++)
        for (int ni = 0; ni < 2; ni++)
            wmma::load_matrix_sync(acc[mi][ni], &biasTile[0][wn + ni * 16], 72,
                                   wmma::mem_row_major);

    const int NT = K / BK;   // 32

    // Prologue: issue tiles 0 and 1
    gemm_issue_tile(sm, 0, Xh, Xl, Wh, Wl, m0, n0, 0, K, tid);
    __pipeline_commit();
    gemm_issue_tile(sm, 1, Xh, Xl, Wh, Wl, m0, n0, BK, K, tid);
    __pipeline_commit();

    for (int t = 0; t < NT; t++) {
        __pipeline_wait_prior(1);      // tile t resident
        __syncthreads();               // + all threads done with tile t-1
        if (t + 2 < NT)
            gemm_issue_tile(sm, (t + 2) % 3, Xh, Xl, Wh, Wl, m0, n0,
                            (t + 2) * BK, K, tid);
        __pipeline_commit();           // always commit (keeps group count stable)

        const __nv_bfloat16* sb = sm + (t % 3) * SE;
        for (int ks = 0; ks < 2; ks++) {
            int kc = ks * 16;
            wmma::fragment<wmma::matrix_b, 16, 16, 16, __nv_bfloat16, wmma::col_major> bh[2], bl[2];
            for (int ni = 0; ni < 2; ni++) {
                int r = wn + ni * 16;
                wmma::load_matrix_sync(bh[ni], sb + BH_OFF + r * LDT + kc, LDT);
                wmma::load_matrix_sync(bl[ni], sb + BL_OFF + r * LDT + kc, LDT);
            }
            for (int mi = 0; mi < 2; mi++) {
                wmma::fragment<wmma::matrix_a, 16, 16, 16, __nv_bfloat16, wmma::row_major> ah, al;
                int r = wm + mi * 16;
                wmma::load_matrix_sync(ah, sb + AH_OFF + r * LDT + kc, LDT);
                wmma::load_matrix_sync(al, sb + AL_OFF + r * LDT + kc, LDT);
                for (int ni = 0; ni < 2; ni++) {
                    wmma::mma_sync(acc[mi][ni], ah, bh[ni], acc[mi][ni]);
                    wmma::mma_sync(acc[mi][ni], ah, bl[ni], acc[mi][ni]);
                    wmma::mma_sync(acc[mi][ni], al, bh[ni], acc[mi][ni]);
                }
            }
        }
    }

    for (int mi = 0; mi < 2; mi++) {
        for (int ni = 0; ni < 2; ni++) {
            int row = m0 + wm + mi * 16;
            int col = n0 + wn + ni * 16;
            wmma::store_matrix_sync(&Y[(size_t)row * N + col], acc[mi][ni], N,
                                    wmma::mem_row_major);
        }
    }
}

// ---------------------------------------------------------------------------
// Flash attention v3 (causal), fp32, 2 threads/query, 3-stage cp.async ring
// for K/V tiles (1 sync per tile, load latency hidden).
// ---------------------------------------------------------------------------
__device__ __forceinline__ void flash_issue_tile(
    float* fsm, int stage,
    const float* __restrict__ Kp, const float* __restrict__ Vp,
    int b, int h, int kb, int tid)
{
    float* sb = fsm + stage * FSE;
    for (int p = 0; p < 4; p++) {
        int idx = tid + p * 256;     // 0..1023
        int r   = idx >> 4;          // 0..63
        int c   = idx & 15;          // float4 col
        size_t g = ((size_t)b * S_ + kb + r) * D_ + h * DK_ + c * 4;
        __pipeline_memcpy_async(sb + r * 64 + c * 4, Kp + g, 16);
        __pipeline_memcpy_async(sb + 4096 + r * 64 + c * 4, Vp + g, 16);
    }
}

__global__ __launch_bounds__(256)
void flash_attn_kernel(const float* __restrict__ Qp,
                       const float* __restrict__ Kp,
                       const float* __restrict__ Vp,
                       float* __restrict__ O)
{
    extern __shared__ float fsm[];

    const int tid   = threadIdx.x;
    const int t     = tid >> 1;
    const int half  = tid & 1;
    const int qtile = blockIdx.x;
    const int bh    = blockIdx.y;
    const int b     = bh / H_;
    const int h     = bh % H_;
    const int qi    = qtile * 128 + t;
    const int hoff  = half * 32;

    const float* qrow = &Qp[((size_t)b * S_ + qi) * D_ + h * DK_ + hoff];
    float q[32];
#pragma unroll
    for (int d4 = 0; d4 < 8; d4++) {
        float4 v = *(const float4*)&qrow[d4 * 4];
        q[d4*4+0] = v.x; q[d4*4+1] = v.y; q[d4*4+2] = v.z; q[d4*4+3] = v.w;
    }

    float acc[32];
#pragma unroll
    for (int d = 0; d < 32; d++) acc[d] = 0.f;
    float m = -INFINITY;
    float l = 0.f;

    const int ntiles = qtile * 2 + 2;

    flash_issue_tile(fsm, 0, Kp, Vp, b, h, 0, tid);
    __pipeline_commit();
    flash_issue_tile(fsm, 1, Kp, Vp, b, h, 64, tid);
    __pipeline_commit();

    for (int kt = 0; kt < ntiles; kt++) {
        __pipeline_wait_prior(1);
        __syncthreads();
        if (kt + 2 < ntiles)
            flash_issue_tile(fsm, (kt + 2) % 3, Kp, Vp, b, h, (kt + 2) * 64, tid);
        __pipeline_commit();

        const float* Ks = fsm + (kt % 3) * FSE;
        const float* Vs = Ks + 4096;
        const int kb = kt * 64;

        for (int j0 = 0; j0 < 64; j0 += 8) {
            float s[8];
#pragma unroll
            for (int jj = 0; jj < 8; jj++) {
                float sj = 0.f;
                const float* kr = Ks + (j0 + jj) * 64 + hoff;
#pragma unroll
                for (int d4 = 0; d4 < 8; d4++) {
                    float4 kv = *(const float4*)&kr[d4 * 4];
                    sj = fmaf(q[d4*4+0], kv.x, sj);
                    sj = fmaf(q[d4*4+1], kv.y, sj);
                    sj = fmaf(q[d4*4+2], kv.z, sj);
                    sj = fmaf(q[d4*4+3], kv.w, sj);
                }
                sj += __shfl_xor_sync(0xffffffffu, sj, 1);
                int kj = kb + j0 + jj;
                s[jj] = (kj <= qi) ? sj * 0.125f : -1e9f;
            }
            float mt = m;
#pragma unroll
            for (int jj = 0; jj < 8; jj++) mt = fmaxf(mt, s[jj]);
            float scale = __expf(m - mt);
            float p[8];
            float ls = 0.f;
#pragma unroll
            for (int jj = 0; jj < 8; jj++) {
                p[jj] = __expf(s[jj] - mt);
                ls += p[jj];
            }
            l = l * scale + ls;
            m = mt;
#pragma unroll
            for (int d = 0; d < 32; d++) acc[d] *= scale;
#pragma unroll
            for (int jj = 0; jj < 8; jj++) {
                float pj = p[jj];
                const float* vr = Vs + (j0 + jj) * 64 + hoff;
#pragma unroll
                for (int d4 = 0; d4 < 8; d4++) {
                    float4 vv = *(const float4*)&vr[d4 * 4];
                    acc[d4*4+0] = fmaf(pj, vv.x, acc[d4*4+0]);
                    acc[d4*4+1] = fmaf(pj, vv.y, acc[d4*4+1]);
                    acc[d4*4+2] = fmaf(pj, vv.z, acc[d4*4+2]);
                    acc[d4*4+3] = fmaf(pj, vv.w, acc[d4*4+3]);
                }
            }
        }
    }

    const float inv = 1.f / l;
    float* orow = &O[((size_t)b * S_ + qi) * D_ + h * DK_ + hoff];
#pragma unroll
    for (int d4 = 0; d4 < 8; d4++) {
        float4 o;
        o.x = acc[d4*4+0] * inv;
        o.y = acc[d4*4+1] * inv;
        o.z = acc[d4*4+2] * inv;
        o.w = acc[d4*4+3] * inv;
        *(float4*)&orow[d4 * 4] = o;
    }
}

// ---------------------------------------------------------------------------
// Launch. Inputs: q,k,v,mask,Wq,bq,Wk,bk,Wv,bv,Wo,bo
// ---------------------------------------------------------------------------
extern "C" void kernel_launch(void* const* d_in, const int* in_sizes, int n_in,
                              void* d_out, int out_size)
{
    const float* q    = (const float*)d_in[0];
    const float* k    = (const float*)d_in[1];
    const float* v    = (const float*)d_in[2];
    const float* Wq   = (const float*)d_in[4];
    const float* bq   = (const float*)d_in[5];
    const float* Wk   = (const float*)d_in[6];
    const float* bk   = (const float*)d_in[7];
    const float* Wv   = (const float*)d_in[8];
    const float* bv   = (const float*)d_in[9];
    const float* Wo   = (const float*)d_in[10];
    const float* bo   = (const float*)d_in[11];
    float* out = (float*)d_out;

    float *Qp;
    float *Kp;
    float *Vp;
    float *O;
    __nv_bfloat16 *Xh;
    __nv_bfloat16 *Xl;
    __nv_bfloat16 *Wh;
    __nv_bfloat16 *Wl;
    cudaGetSymbolAddress((void**)&Qp, g_Qp);
    cudaGetSymbolAddress((void**)&Kp, g_Kp);
    cudaGetSymbolAddress((void**)&Vp, g_Vp);
    cudaGetSymbolAddress((void**)&O,  g_O);
    cudaGetSymbolAddress((void**)&Xh, g_Xh);
    cudaGetSymbolAddress((void**)&Xl, g_Xl);
    cudaGetSymbolAddress((void**)&Wh, g_Wh);
    cudaGetSymbolAddress((void**)&Wl, g_Wl);

    cudaFuncSetAttribute(gemm_wmma_kernel,
                         cudaFuncAttributeMaxDynamicSharedMemorySize, GEMM_SMEM);
    cudaFuncSetAttribute(flash_attn_kernel,
                         cudaFuncAttributeMaxDynamicSharedMemorySize, FLASH_SMEM);

    const int nX4 = M_ * D_ / 4;
    const int nW4 = D_ * D_ / 4;
    dim3 cvtX((nX4 + 255) / 256);
    dim3 cvtW((nW4 + 255) / 256);
    dim3 ggrid(D_ / BN, M_ / BM);   // (16, 32)

    // Q projection
    cvt_split_kernel<<<cvtX, 256>>>((const float4*)q,  Xh, Xl, nX4);
    cvt_split_kernel<<<cvtW, 256>>>((const float4*)Wq, Wh, Wl, nW4);
    gemm_wmma_kernel<<<ggrid, 256, GEMM_SMEM>>>(Xh, Xl, Wh, Wl, bq, Qp, M_, D_, D_);
    // K projection
    cvt_split_kernel<<<cvtX, 256>>>((const float4*)k,  Xh, Xl, nX4);
    cvt_split_kernel<<<cvtW, 256>>>((const float4*)Wk, Wh, Wl, nW4);
    gemm_wmma_kernel<<<ggrid, 256, GEMM_SMEM>>>(Xh, Xl, Wh, Wl, bk, Kp, M_, D_, D_);
    // V projection
    cvt_split_kernel<<<cvtX, 256>>>((const float4*)v,  Xh, Xl, nX4);
    cvt_split_kernel<<<cvtW, 256>>>((const float4*)Wv, Wh, Wl, nW4);
    gemm_wmma_kernel<<<ggrid, 256, GEMM_SMEM>>>(Xh, Xl, Wh, Wl, bv, Vp, M_, D_, D_);

    // Attention
    dim3 fgrid(S_ / 128, B_ * H_);
    flash_attn_kernel<<<fgrid, 256, FLASH_SMEM>>>(Qp, Kp, Vp, O);

    // Output projection
    cvt_split_kernel<<<cvtX, 256>>>((const float4*)O,  Xh, Xl, nX4);
    cvt_split_kernel<<<cvtW, 256>>>((const float4*)Wo, Wh, Wl, nW4);
    gemm_wmma_kernel<<<ggrid, 256, GEMM_SMEM>>>(Xh, Xl, Wh, Wl, bo, out, M_, D_, D_);
}